// round 3
// baseline (speedup 1.0000x reference)
#include <cuda_runtime.h>
#include <cuda_bf16.h>

#define N_ATOMS 100000
#define E_ATOMS 200000
#define N_AMINO 10240
#define E_AMINO 20480
#define BGRAPH  512
#define D_IN    40
#define D_E     11
#define H       20
#define D_AA    8
#define F_IN    28
#define H_ARMA  128
#define K_ST    3
#define T_LAY   7
#define F1      256
#define F2      128
#define F3      64
#define NCOMB   260     // 220 (z) + 20 (xb) + 20 (root-init)
#define KC      32      // gemm K-chunk

// ------------------------- scratch (device globals) -------------------------
__device__ float g_cn1[(long)N_ATOMS * NCOMB];
__device__ float g_cn2[(long)N_ATOMS * NCOMB];
__device__ float g_wpack[3][D_IN * NCOMB];
__device__ float g_bpack[3][NCOMB];
__device__ float g_aa[N_AMINO * F_IN];
__device__ float g_norm[E_AMINO];
__device__ float g_tmp [K_ST * N_AMINO * H_ARMA];
__device__ float g_accA[K_ST * N_AMINO * H_ARMA];
__device__ float g_accB[K_ST * N_AMINO * H_ARMA];
__device__ float g_pool[BGRAPH * H_ARMA];
__device__ float g_p1[BGRAPH * F1];
__device__ float g_p2[BGRAPH * F2];
__device__ float g_p3[BGRAPH * F3];
// CSR scratch
__device__ int g_off_atom[N_ATOMS + 1];
__device__ int g_cur_atom[N_ATOMS];
__device__ int g_list_atom[E_ATOMS];
__device__ int g_off_lab[N_AMINO + 1];
__device__ int g_cur_lab[N_AMINO];
__device__ int g_list_lab[N_ATOMS];
__device__ int g_off_am[N_AMINO + 1];
__device__ int g_cur_am[N_AMINO];
__device__ int g_list_am[E_AMINO];
__device__ int g_bsum[1024];
__device__ int g_bsumX[1024];
__device__ int g_dummy[4];
__device__ int g_start[BGRAPH + 1];

// ------------------------- register-tiled GEMM (K-chunked) -------------------------
// C[b][m][n] = bias[b][n] + sum_k relu?(A[b][m][k]) * W[b][k][n]
// BM=128, BN=64, 128 threads, 8x8 per thread. Kd % 4 == 0.
__global__ void __launch_bounds__(128) gemm_tiled(
        const float* __restrict__ A, int lda, long strideA,
        const float* __restrict__ W, long strideW,
        const float* __restrict__ Bias, long strideB,
        float* __restrict__ C, int ldc, long strideC,
        int M, int Kd, int N, int reluA)
{
    const int BM = 128, BN = 64;
    __shared__ float sA[BM][KC + 1];
    __shared__ float sW[KC][BN];

    int b = blockIdx.z;
    const float* Ab = A + (long)b * strideA;
    const float* Wb = W + (long)b * strideW;
    float*       Cb = C + (long)b * strideC;
    int m0 = blockIdx.x * BM;
    int n0 = blockIdx.y * BN;
    int tid = threadIdx.x;

    int ct = tid & 7;
    int rt = tid >> 3;
    int mbase = rt * 8;
    int nb = ct * 8;

    float acc[8][8];
    #pragma unroll
    for (int i = 0; i < 8; i++)
        #pragma unroll
        for (int j = 0; j < 8; j++) acc[i][j] = 0.f;

    for (int kc0 = 0; kc0 < Kd; kc0 += KC) {
        int kc = min(KC, Kd - kc0);
        // stage W chunk [kc][BN]
        int wtot = kc * (BN / 4);
        for (int idx = tid; idx < wtot; idx += 128) {
            int k  = idx >> 4;
            int n4 = (idx & 15) << 2;
            int n  = n0 + n4;
            const float* wr = Wb + (long)(kc0 + k) * N;
            float4 w;
            if (n + 3 < N) w = *(const float4*)(wr + n);
            else {
                w.x = (n     < N) ? wr[n]     : 0.f;
                w.y = (n + 1 < N) ? wr[n + 1] : 0.f;
                w.z = (n + 2 < N) ? wr[n + 2] : 0.f;
                w.w = (n + 3 < N) ? wr[n + 3] : 0.f;
            }
            *(float4*)(&sW[k][n4]) = w;
        }
        // stage A chunk [BM][kc]
        int kq = kc >> 2;
        int atot = BM * kq;
        for (int idx = tid; idx < atot; idx += 128) {
            int m  = idx / kq;
            int k4 = (idx - m * kq) << 2;
            int row = m0 + m;
            float4 a = make_float4(0.f, 0.f, 0.f, 0.f);
            if (row < M) a = *(const float4*)(Ab + (long)row * lda + kc0 + k4);
            if (reluA) {
                a.x = fmaxf(a.x, 0.f); a.y = fmaxf(a.y, 0.f);
                a.z = fmaxf(a.z, 0.f); a.w = fmaxf(a.w, 0.f);
            }
            sA[m][k4] = a.x; sA[m][k4+1] = a.y; sA[m][k4+2] = a.z; sA[m][k4+3] = a.w;
        }
        __syncthreads();
        for (int k = 0; k < kc; k++) {
            float4 w0 = *(const float4*)(&sW[k][nb]);
            float4 w1 = *(const float4*)(&sW[k][nb + 4]);
            #pragma unroll
            for (int i = 0; i < 8; i++) {
                float a = sA[mbase + i][k];
                acc[i][0] = fmaf(a, w0.x, acc[i][0]);
                acc[i][1] = fmaf(a, w0.y, acc[i][1]);
                acc[i][2] = fmaf(a, w0.z, acc[i][2]);
                acc[i][3] = fmaf(a, w0.w, acc[i][3]);
                acc[i][4] = fmaf(a, w1.x, acc[i][4]);
                acc[i][5] = fmaf(a, w1.y, acc[i][5]);
                acc[i][6] = fmaf(a, w1.z, acc[i][6]);
                acc[i][7] = fmaf(a, w1.w, acc[i][7]);
            }
        }
        __syncthreads();
    }

    float bv[8];
    #pragma unroll
    for (int j = 0; j < 8; j++) {
        int n = n0 + nb + j;
        bv[j] = (Bias && n < N) ? Bias[(long)b * strideB + n] : 0.f;
    }
    bool fullN = (n0 + nb + 7) < N;
    #pragma unroll
    for (int i = 0; i < 8; i++) {
        int row = m0 + mbase + i;
        if (row >= M) break;
        float* cr = Cb + (long)row * ldc + n0 + nb;
        if (fullN) {
            float4 o0 = make_float4(acc[i][0]+bv[0], acc[i][1]+bv[1], acc[i][2]+bv[2], acc[i][3]+bv[3]);
            float4 o1 = make_float4(acc[i][4]+bv[4], acc[i][5]+bv[5], acc[i][6]+bv[6], acc[i][7]+bv[7]);
            *(float4*)(cr)     = o0;
            *(float4*)(cr + 4) = o1;
        } else {
            #pragma unroll
            for (int j = 0; j < 8; j++) {
                int n = n0 + nb + j;
                if (n < N) cr[j] = acc[i][j] + bv[j];
            }
        }
    }
}

// ------------------------- CSR build -------------------------
__global__ void zero3_k(int* a, int na, int* b, int nb_, int* c, int nc)
{
    int i = blockIdx.x * blockDim.x + threadIdx.x;
    if (i < na) a[i] = 0;
    if (i < nb_) b[i] = 0;
    if (i < nc) c[i] = 0;
}

__global__ void count3_k(const int* __restrict__ eiDst, const int* __restrict__ lab,
                         const int* __restrict__ aeiDst,
                         int* cA, int* cL, int* cM)
{
    int i = blockIdx.x * blockDim.x + threadIdx.x;
    if (i < E_ATOMS) atomicAdd(&cA[eiDst[i]], 1);
    if (i < N_ATOMS) atomicAdd(&cL[lab[i]], 1);
    if (i < E_AMINO) atomicAdd(&cM[aeiDst[i]], 1);
}

// per-block exclusive scan of 1024 ints; writes block total to bsum.
__global__ void scan_block(const int* __restrict__ in, int n,
                           int* __restrict__ out, int* __restrict__ bsum)
{
    __shared__ int s[256];
    int tid = threadIdx.x;
    int base = blockIdx.x * 1024 + tid * 4;
    int v0 = (base     < n) ? in[base]     : 0;
    int v1 = (base + 1 < n) ? in[base + 1] : 0;
    int v2 = (base + 2 < n) ? in[base + 2] : 0;
    int v3 = (base + 3 < n) ? in[base + 3] : 0;
    int sum = v0 + v1 + v2 + v3;
    s[tid] = sum;
    __syncthreads();
    for (int off = 1; off < 256; off <<= 1) {
        int val = s[tid];
        if (tid >= off) val += s[tid - off];
        __syncthreads();
        s[tid] = val;
        __syncthreads();
    }
    int run = s[tid] - sum;   // exclusive base for this thread's chunk
    if (base     < n) out[base]     = run;           run += v0;
    if (base + 1 < n) out[base + 1] = run;           run += v1;
    if (base + 2 < n) out[base + 2] = run;           run += v2;
    if (base + 3 < n) out[base + 3] = run;
    if (tid == 255) bsum[blockIdx.x] = s[255];
}

// off[i] += bsumX[i/1024]; cursor = off; off[m] = total
__global__ void scan_fixup(int* __restrict__ off, int* __restrict__ cur, int m,
                           const int* __restrict__ bsumX, int total)
{
    int i = blockIdx.x * blockDim.x + threadIdx.x;
    if (i < m) {
        int v = off[i] + bsumX[i >> 10];
        off[i] = v;
        cur[i] = v;
    }
    if (i == 0) off[m] = total;
}

__global__ void fill3_k(const int* __restrict__ eiDst, const int* __restrict__ lab,
                        const int* __restrict__ aeiDst,
                        int* curA, int* listA, int* curL, int* listL,
                        int* curM, int* listM)
{
    int i = blockIdx.x * blockDim.x + threadIdx.x;
    if (i < E_ATOMS) { int p = atomicAdd(&curA[eiDst[i]], 1); listA[p] = i; }
    if (i < N_ATOMS) { int p = atomicAdd(&curL[lab[i]], 1);  listL[p] = i; }
    if (i < E_AMINO) { int p = atomicAdd(&curM[aeiDst[i]], 1); listM[p] = i; }
}

// ------------------------- NNConv -------------------------
__global__ void pack_nn(const float* __restrict__ nw, const float* __restrict__ nb,
                        const float* __restrict__ root, const float* __restrict__ b,
                        float* __restrict__ Wp, float* __restrict__ bp, int d_in)
{
    int idx = blockIdx.x * blockDim.x + threadIdx.x;
    int total = d_in * NCOMB;
    if (idx < total) {
        int i = idx / NCOMB, c = idx % NCOMB;
        float v;
        if (c < 220)      { int d = c / H, o = c % H; v = nw[d * (d_in * H) + i * H + o]; }
        else if (c < 240) { v = nb[i * H + (c - 220)]; }
        else              { v = root[i * H + (c - 240)]; }
        Wp[idx] = v;
    }
    if (idx < NCOMB) bp[idx] = (idx < 240) ? 0.f : b[idx - 240];
}

// gather messages into acc cols (single writer, no atomics)
__global__ void nnconv_gather(const int* __restrict__ off, const int* __restrict__ list,
                              const int* __restrict__ eiSrc, const float* __restrict__ ea,
                              float* __restrict__ Cn)
{
    int idx = blockIdx.x * blockDim.x + threadIdx.x;
    if (idx >= N_ATOMS * H) return;
    int dst = idx / H, o = idx - dst * H;
    long cbase = (long)dst * NCOMB + 240 + o;
    float s = Cn[cbase];               // root + bias, from GEMM
    int p0 = off[dst], p1 = off[dst + 1];
    for (int p = p0; p < p1; p++) {
        int e = list[p];
        int src = eiSrc[e];
        const float* zrow = Cn + (long)src * NCOMB;
        const float* eav = ea + (long)e * D_E;
        float m = zrow[220 + o];
        #pragma unroll
        for (int d = 0; d < D_E; d++) m = fmaf(eav[d], zrow[d * H + o], m);
        s += m;
    }
    Cn[cbase] = s;
}

// ------------------------- amino stage -------------------------
// aa[n, 0:20] = sum over atoms of relu(acc); aa[n, 20:28] = features
__global__ void atom2aa_gather(const int* __restrict__ off, const int* __restrict__ list,
                               const float* __restrict__ Cn, const float* __restrict__ feat,
                               float* __restrict__ aa)
{
    int idx = blockIdx.x * blockDim.x + threadIdx.x;
    if (idx >= N_AMINO * F_IN) return;
    int n = idx / F_IN, c = idx - n * F_IN;
    if (c < H) {
        float s = 0.f;
        int p0 = off[n], p1 = off[n + 1];
        for (int p = p0; p < p1; p++)
            s += fmaxf(Cn[(long)list[p] * NCOMB + 240 + c], 0.f);
        aa[idx] = s;
    } else {
        aa[idx] = feat[n * D_AA + (c - H)];
    }
}

__global__ void norm_k(const int* __restrict__ aei, const int* __restrict__ off,
                       float* __restrict__ nrm)
{
    int e = blockIdx.x * blockDim.x + threadIdx.x;
    if (e >= E_AMINO) return;
    int src = aei[e], dst = aei[E_AMINO + e];
    float ds = (float)(off[src + 1] - off[src]);
    float dd = (float)(off[dst + 1] - off[dst]);
    float a = (ds > 0.f) ? rsqrtf(ds) : 0.f;
    float c = (dd > 0.f) ? rsqrtf(dd) : 0.f;
    nrm[e] = a * c;
}

__global__ void arma_gather(const int* __restrict__ off, const int* __restrict__ list,
                            const int* __restrict__ aeiSrc, const float* __restrict__ nrm,
                            const float* __restrict__ tmp, float* __restrict__ acc)
{
    int idx = blockIdx.x * blockDim.x + threadIdx.x;
    if (idx >= K_ST * N_AMINO * H_ARMA) return;
    int o = idx & (H_ARMA - 1);
    int r = idx >> 7;
    int n = r % N_AMINO;
    int k = r / N_AMINO;
    float s = acc[idx];                // aa@root + bias, from GEMM
    long kb = (long)k * N_AMINO;
    int p0 = off[n], p1 = off[n + 1];
    for (int p = p0; p < p1; p++) {
        int e = list[p];
        s = fmaf(nrm[e], tmp[(kb + aeiSrc[e]) * H_ARMA + o], s);
    }
    acc[idx] = s;
}

__global__ void starts_k(const int* __restrict__ ab, int* __restrict__ start)
{
    int n = blockIdx.x * blockDim.x + threadIdx.x;
    if (n >= N_AMINO) return;
    int b = ab[n];
    int prev = (n == 0) ? -1 : ab[n - 1];
    for (int g = prev + 1; g <= b; g++) start[g] = n;
    if (n == N_AMINO - 1)
        for (int g = b + 1; g <= BGRAPH; g++) start[g] = N_AMINO;
}

__global__ void pool_gather(const float* __restrict__ acc, const int* __restrict__ start,
                            float* __restrict__ g)
{
    int idx = blockIdx.x * blockDim.x + threadIdx.x;
    if (idx >= BGRAPH * H_ARMA) return;
    int b = idx >> 7, o = idx & (H_ARMA - 1);
    int n0 = start[b], n1 = start[b + 1];
    float s = 0.f;
    for (int n = n0; n < n1; n++) {
        #pragma unroll
        for (int k = 0; k < K_ST; k++)
            s += fmaxf(acc[((long)k * N_AMINO + n) * H_ARMA + o], 0.f);
    }
    g[idx] = s * (1.f / 3.f);
}

__global__ void final_k(const float* __restrict__ p3, const float* __restrict__ w,
                        const float* __restrict__ b, float* __restrict__ out)
{
    int i = blockIdx.x * blockDim.x + threadIdx.x;
    if (i >= BGRAPH) return;
    float s = b[0];
    #pragma unroll
    for (int f = 0; f < F3; f++) s = fmaf(fmaxf(p3[i * F3 + f], 0.f), w[f], s);
    out[i] = s;
}

// ------------------------- host orchestration -------------------------
static inline int ceil_div(long a, int b) { return (int)((a + b - 1) / b); }

extern "C" void kernel_launch(void* const* d_in, const int* in_sizes, int n_in,
                              void* d_out, int out_size)
{
    const float* x     = (const float*)d_in[0];
    const int*   ei    = (const int*)  d_in[1];
    const float* ea    = (const float*)d_in[2];
    const int*   lab   = (const int*)  d_in[3];
    const float* feat  = (const float*)d_in[4];
    const int*   aei   = (const int*)  d_in[5];
    const int*   ab    = (const int*)  d_in[6];
    const float* nn1_w = (const float*)d_in[7];
    const float* nn1_b = (const float*)d_in[8];
    const float* root1 = (const float*)d_in[9];
    const float* b1    = (const float*)d_in[10];
    const float* nn2_w = (const float*)d_in[11];
    const float* nn2_b = (const float*)d_in[12];
    const float* root2 = (const float*)d_in[13];
    const float* b2    = (const float*)d_in[14];
    const float* nn3_w = (const float*)d_in[15];
    const float* nn3_b = (const float*)d_in[16];
    const float* root3 = (const float*)d_in[17];
    const float* b3    = (const float*)d_in[18];
    const float* arma_init = (const float*)d_in[19];
    const float* arma_w    = (const float*)d_in[20];
    const float* arma_root = (const float*)d_in[21];
    const float* arma_bias = (const float*)d_in[22];
    const float* l1_w = (const float*)d_in[23];
    const float* l1_b = (const float*)d_in[24];
    const float* l2_w = (const float*)d_in[25];
    const float* l2_b = (const float*)d_in[26];
    const float* l3_w = (const float*)d_in[27];
    const float* l3_b = (const float*)d_in[28];
    const float* l4_w = (const float*)d_in[29];
    const float* l4_b = (const float*)d_in[30];

    float *cn1, *cn2, *wp, *bp, *aa, *nrm, *tmp, *accA, *accB, *pool, *p1, *p2, *p3;
    int *offA, *curA, *listA, *offL, *curL, *listL, *offM, *curM, *listM;
    int *bsum, *bsumX, *dummy, *startp;
    cudaGetSymbolAddress((void**)&cn1,  g_cn1);
    cudaGetSymbolAddress((void**)&cn2,  g_cn2);
    cudaGetSymbolAddress((void**)&wp,   g_wpack);
    cudaGetSymbolAddress((void**)&bp,   g_bpack);
    cudaGetSymbolAddress((void**)&aa,   g_aa);
    cudaGetSymbolAddress((void**)&nrm,  g_norm);
    cudaGetSymbolAddress((void**)&tmp,  g_tmp);
    cudaGetSymbolAddress((void**)&accA, g_accA);
    cudaGetSymbolAddress((void**)&accB, g_accB);
    cudaGetSymbolAddress((void**)&pool, g_pool);
    cudaGetSymbolAddress((void**)&p1,   g_p1);
    cudaGetSymbolAddress((void**)&p2,   g_p2);
    cudaGetSymbolAddress((void**)&p3,   g_p3);
    cudaGetSymbolAddress((void**)&offA, g_off_atom);
    cudaGetSymbolAddress((void**)&curA, g_cur_atom);
    cudaGetSymbolAddress((void**)&listA, g_list_atom);
    cudaGetSymbolAddress((void**)&offL, g_off_lab);
    cudaGetSymbolAddress((void**)&curL, g_cur_lab);
    cudaGetSymbolAddress((void**)&listL, g_list_lab);
    cudaGetSymbolAddress((void**)&offM, g_off_am);
    cudaGetSymbolAddress((void**)&curM, g_cur_am);
    cudaGetSymbolAddress((void**)&listM, g_list_am);
    cudaGetSymbolAddress((void**)&bsum, g_bsum);
    cudaGetSymbolAddress((void**)&bsumX, g_bsumX);
    cudaGetSymbolAddress((void**)&dummy, g_dummy);
    cudaGetSymbolAddress((void**)&startp, g_start);

    const int TB = 256;
    const int* eiSrc  = ei;
    const int* eiDst  = ei + E_ATOMS;
    const int* aeiSrc = aei;
    const int* aeiDst = aei + E_AMINO;

    // ================= CSR builds (reused across layers) =================
    zero3_k<<<ceil_div(N_ATOMS, TB), TB>>>(curA, N_ATOMS, curL, N_AMINO, curM, N_AMINO);
    count3_k<<<ceil_div(E_ATOMS, TB), TB>>>(eiDst, lab, aeiDst, curA, curL, curM);
    // scans (1024 elems/block)
    scan_block<<<ceil_div(N_ATOMS, 1024), 256>>>(curA, N_ATOMS, offA, bsum);
    scan_block<<<1, 256>>>(bsum, ceil_div(N_ATOMS, 1024), bsumX, dummy);
    scan_fixup<<<ceil_div(N_ATOMS, TB), TB>>>(offA, curA, N_ATOMS, bsumX, E_ATOMS);
    scan_block<<<ceil_div(N_AMINO, 1024), 256>>>(curL, N_AMINO, offL, bsum);
    scan_block<<<1, 256>>>(bsum, ceil_div(N_AMINO, 1024), bsumX, dummy);
    scan_fixup<<<ceil_div(N_AMINO, TB), TB>>>(offL, curL, N_AMINO, bsumX, N_ATOMS);
    scan_block<<<ceil_div(N_AMINO, 1024), 256>>>(curM, N_AMINO, offM, bsum);
    scan_block<<<1, 256>>>(bsum, ceil_div(N_AMINO, 1024), bsumX, dummy);
    scan_fixup<<<ceil_div(N_AMINO, TB), TB>>>(offM, curM, N_AMINO, bsumX, E_AMINO);
    fill3_k<<<ceil_div(E_ATOMS, TB), TB>>>(eiDst, lab, aeiDst,
                                           curA, listA, curL, listL, curM, listM);
    norm_k<<<ceil_div(E_AMINO, TB), TB>>>(aei, offM, nrm);
    starts_k<<<ceil_div(N_AMINO, TB), TB>>>(ab, startp);

    // ================= NNConv layers =================
    dim3 gN1(ceil_div(N_ATOMS, 128), ceil_div(NCOMB, 64), 1);
    int gatherBlocks = ceil_div(N_ATOMS * H, TB);

    pack_nn<<<ceil_div(D_IN * NCOMB, TB), TB>>>(nn1_w, nn1_b, root1, b1,
                                                wp, bp, D_IN);
    pack_nn<<<ceil_div(H * NCOMB, TB), TB>>>(nn2_w, nn2_b, root2, b2,
                                             wp + D_IN * NCOMB, bp + NCOMB, H);
    pack_nn<<<ceil_div(H * NCOMB, TB), TB>>>(nn3_w, nn3_b, root3, b3,
                                             wp + 2 * D_IN * NCOMB, bp + 2 * NCOMB, H);

    gemm_tiled<<<gN1, 128>>>(x, D_IN, 0, wp, 0, bp, 0,
                             cn1, NCOMB, 0, N_ATOMS, D_IN, NCOMB, 0);
    nnconv_gather<<<gatherBlocks, TB>>>(offA, listA, eiSrc, ea, cn1);

    gemm_tiled<<<gN1, 128>>>(cn1 + 240, NCOMB, 0, wp + D_IN * NCOMB, 0, bp + NCOMB, 0,
                             cn2, NCOMB, 0, N_ATOMS, H, NCOMB, 1);
    nnconv_gather<<<gatherBlocks, TB>>>(offA, listA, eiSrc, ea, cn2);

    gemm_tiled<<<gN1, 128>>>(cn2 + 240, NCOMB, 0, wp + 2 * D_IN * NCOMB, 0, bp + 2 * NCOMB, 0,
                             cn1, NCOMB, 0, N_ATOMS, H, NCOMB, 1);
    nnconv_gather<<<gatherBlocks, TB>>>(offA, listA, eiSrc, ea, cn1);

    // ================= atoms -> amino =================
    atom2aa_gather<<<ceil_div(N_AMINO * F_IN, TB), TB>>>(offL, listL, cn1, feat, aa);

    // ================= ARMA: K=3 stacks, T=7 layers =================
    dim3 gArma(ceil_div(N_AMINO, 128), 2, K_ST);
    int armaGB = ceil_div(K_ST * N_AMINO * H_ARMA, TB);
    float* accP = accA;
    float* accN = accB;
    for (int t = 0; t < T_LAY; t++) {
        if (t == 0) {
            gemm_tiled<<<gArma, 128>>>(
                aa, F_IN, 0,
                arma_init, (long)F_IN * H_ARMA, nullptr, 0,
                tmp, H_ARMA, (long)N_AMINO * H_ARMA,
                N_AMINO, F_IN, H_ARMA, 0);
        } else {
            gemm_tiled<<<gArma, 128>>>(
                accP, H_ARMA, (long)N_AMINO * H_ARMA,
                arma_w + (long)(t - 1) * K_ST * H_ARMA * H_ARMA, (long)H_ARMA * H_ARMA,
                nullptr, 0,
                tmp, H_ARMA, (long)N_AMINO * H_ARMA,
                N_AMINO, H_ARMA, H_ARMA, 1);
        }
        gemm_tiled<<<gArma, 128>>>(
            aa, F_IN, 0,
            arma_root + (long)t * K_ST * F_IN * H_ARMA, (long)F_IN * H_ARMA,
            arma_bias + (long)t * K_ST * H_ARMA, H_ARMA,
            accN, H_ARMA, (long)N_AMINO * H_ARMA,
            N_AMINO, F_IN, H_ARMA, 0);
        arma_gather<<<armaGB, TB>>>(offM, listM, aeiSrc, nrm, tmp, accN);
        float* t2 = accP; accP = accN; accN = t2;
    }

    // ================= pooling + head =================
    pool_gather<<<ceil_div(BGRAPH * H_ARMA, TB), TB>>>(accP, startp, pool);

    dim3 gH1(ceil_div(BGRAPH, 128), ceil_div(F1, 64), 1);
    gemm_tiled<<<gH1, 128>>>(pool, H_ARMA, 0, l1_w, 0, l1_b, 0,
                             p1, F1, 0, BGRAPH, H_ARMA, F1, 0);
    dim3 gH2(ceil_div(BGRAPH, 128), ceil_div(F2, 64), 1);
    gemm_tiled<<<gH2, 128>>>(p1, F1, 0, l2_w, 0, l2_b, 0,
                             p2, F2, 0, BGRAPH, F1, F2, 1);
    dim3 gH3(ceil_div(BGRAPH, 128), ceil_div(F3, 64), 1);
    gemm_tiled<<<gH3, 128>>>(p2, F2, 0, l3_w, 0, l3_b, 0,
                             p3, F3, 0, BGRAPH, F2, F3, 1);
    final_k<<<ceil_div(BGRAPH, TB), TB>>>(p3, l4_w, l4_b, (float*)d_out);
}

// round 4
// speedup vs baseline: 1.0362x; 1.0362x over previous
#include <cuda_runtime.h>
#include <cuda_bf16.h>

#define N_ATOMS 100000
#define E_ATOMS 200000
#define N_AMINO 10240
#define E_AMINO 20480
#define BGRAPH  512
#define D_IN    40
#define D_E     11
#define H       20
#define D_AA    8
#define F_IN    28
#define H_ARMA  128
#define K_ST    3
#define T_LAY   7
#define F1      256
#define F2      128
#define F3      64
#define NCOMB   260     // 220 (z) + 20 (xb) + 20 (root-init)
#define KC      32      // gemm K-chunk

// ------------------------- scratch (device globals) -------------------------
__device__ float g_cn1[(long)N_ATOMS * NCOMB];
__device__ float g_cn2[(long)N_ATOMS * NCOMB];
__device__ float g_wpack[3][D_IN * NCOMB];
__device__ float g_bpack[3][NCOMB];
__device__ float g_aa[N_AMINO * F_IN];
__device__ float g_norm[E_AMINO];
__device__ float g_tmp [K_ST * N_AMINO * H_ARMA];
__device__ float g_accA[K_ST * N_AMINO * H_ARMA];
__device__ float g_accB[K_ST * N_AMINO * H_ARMA];
__device__ float g_pool[BGRAPH * H_ARMA];
__device__ float g_p1[BGRAPH * F1];
__device__ float g_p2[BGRAPH * F2];
__device__ float g_p3[BGRAPH * F3];
// amino CSR scratch
__device__ int g_off_am[N_AMINO + 1];
__device__ int g_cur_am[N_AMINO];
__device__ int g_list_am[E_AMINO];
__device__ int g_bsum[64];
__device__ int g_bsumX[64];
__device__ int g_dummy[4];
__device__ int g_start[BGRAPH + 1];

// ------------------------- register-tiled GEMM (K-chunked) -------------------------
// C[b][m][n] = bias[b][n] + sum_k relu?(A[b][m][k]) * W[b][k][n]
// BM=128, BN=64, 128 threads, 8x8 per thread. Kd % 4 == 0.
__global__ void __launch_bounds__(128) gemm_tiled(
        const float* __restrict__ A, int lda, long strideA,
        const float* __restrict__ W, long strideW,
        const float* __restrict__ Bias, long strideB,
        float* __restrict__ C, int ldc, long strideC,
        int M, int Kd, int N, int reluA)
{
    const int BM = 128, BN = 64;
    __shared__ float sA[BM][KC + 1];
    __shared__ float sW[KC][BN];

    int b = blockIdx.z;
    const float* Ab = A + (long)b * strideA;
    const float* Wb = W + (long)b * strideW;
    float*       Cb = C + (long)b * strideC;
    int m0 = blockIdx.x * BM;
    int n0 = blockIdx.y * BN;
    int tid = threadIdx.x;

    int ct = tid & 7;
    int rt = tid >> 3;
    int mbase = rt * 8;
    int nb = ct * 8;

    float acc[8][8];
    #pragma unroll
    for (int i = 0; i < 8; i++)
        #pragma unroll
        for (int j = 0; j < 8; j++) acc[i][j] = 0.f;

    for (int kc0 = 0; kc0 < Kd; kc0 += KC) {
        int kc = min(KC, Kd - kc0);
        int wtot = kc * (BN / 4);
        for (int idx = tid; idx < wtot; idx += 128) {
            int k  = idx >> 4;
            int n4 = (idx & 15) << 2;
            int n  = n0 + n4;
            const float* wr = Wb + (long)(kc0 + k) * N;
            float4 w;
            if (n + 3 < N) w = *(const float4*)(wr + n);
            else {
                w.x = (n     < N) ? wr[n]     : 0.f;
                w.y = (n + 1 < N) ? wr[n + 1] : 0.f;
                w.z = (n + 2 < N) ? wr[n + 2] : 0.f;
                w.w = (n + 3 < N) ? wr[n + 3] : 0.f;
            }
            *(float4*)(&sW[k][n4]) = w;
        }
        int kq = kc >> 2;
        int atot = BM * kq;
        for (int idx = tid; idx < atot; idx += 128) {
            int m  = idx / kq;
            int k4 = (idx - m * kq) << 2;
            int row = m0 + m;
            float4 a = make_float4(0.f, 0.f, 0.f, 0.f);
            if (row < M) a = *(const float4*)(Ab + (long)row * lda + kc0 + k4);
            if (reluA) {
                a.x = fmaxf(a.x, 0.f); a.y = fmaxf(a.y, 0.f);
                a.z = fmaxf(a.z, 0.f); a.w = fmaxf(a.w, 0.f);
            }
            sA[m][k4] = a.x; sA[m][k4+1] = a.y; sA[m][k4+2] = a.z; sA[m][k4+3] = a.w;
        }
        __syncthreads();
        for (int k = 0; k < kc; k++) {
            float4 w0 = *(const float4*)(&sW[k][nb]);
            float4 w1 = *(const float4*)(&sW[k][nb + 4]);
            #pragma unroll
            for (int i = 0; i < 8; i++) {
                float a = sA[mbase + i][k];
                acc[i][0] = fmaf(a, w0.x, acc[i][0]);
                acc[i][1] = fmaf(a, w0.y, acc[i][1]);
                acc[i][2] = fmaf(a, w0.z, acc[i][2]);
                acc[i][3] = fmaf(a, w0.w, acc[i][3]);
                acc[i][4] = fmaf(a, w1.x, acc[i][4]);
                acc[i][5] = fmaf(a, w1.y, acc[i][5]);
                acc[i][6] = fmaf(a, w1.z, acc[i][6]);
                acc[i][7] = fmaf(a, w1.w, acc[i][7]);
            }
        }
        __syncthreads();
    }

    float bv[8];
    #pragma unroll
    for (int j = 0; j < 8; j++) {
        int n = n0 + nb + j;
        bv[j] = (Bias && n < N) ? Bias[(long)b * strideB + n] : 0.f;
    }
    bool fullN = (n0 + nb + 7) < N;
    #pragma unroll
    for (int i = 0; i < 8; i++) {
        int row = m0 + mbase + i;
        if (row >= M) break;
        float* cr = Cb + (long)row * ldc + n0 + nb;
        if (fullN) {
            float4 o0 = make_float4(acc[i][0]+bv[0], acc[i][1]+bv[1], acc[i][2]+bv[2], acc[i][3]+bv[3]);
            float4 o1 = make_float4(acc[i][4]+bv[4], acc[i][5]+bv[5], acc[i][6]+bv[6], acc[i][7]+bv[7]);
            *(float4*)(cr)     = o0;
            *(float4*)(cr + 4) = o1;
        } else {
            #pragma unroll
            for (int j = 0; j < 8; j++) {
                int n = n0 + nb + j;
                if (n < N) cr[j] = acc[i][j] + bv[j];
            }
        }
    }
}

// ------------------------- amino CSR build -------------------------
__global__ void zeroM_k(int* c)
{
    int i = blockIdx.x * blockDim.x + threadIdx.x;
    if (i < N_AMINO) c[i] = 0;
}

__global__ void countM_k(const int* __restrict__ aeiDst, int* c)
{
    int i = blockIdx.x * blockDim.x + threadIdx.x;
    if (i < E_AMINO) atomicAdd(&c[aeiDst[i]], 1);
}

__global__ void scan_block(const int* __restrict__ in, int n,
                           int* __restrict__ out, int* __restrict__ bsum)
{
    __shared__ int s[256];
    int tid = threadIdx.x;
    int base = blockIdx.x * 1024 + tid * 4;
    int v0 = (base     < n) ? in[base]     : 0;
    int v1 = (base + 1 < n) ? in[base + 1] : 0;
    int v2 = (base + 2 < n) ? in[base + 2] : 0;
    int v3 = (base + 3 < n) ? in[base + 3] : 0;
    int sum = v0 + v1 + v2 + v3;
    s[tid] = sum;
    __syncthreads();
    for (int off = 1; off < 256; off <<= 1) {
        int val = s[tid];
        if (tid >= off) val += s[tid - off];
        __syncthreads();
        s[tid] = val;
        __syncthreads();
    }
    int run = s[tid] - sum;
    if (base     < n) out[base]     = run;           run += v0;
    if (base + 1 < n) out[base + 1] = run;           run += v1;
    if (base + 2 < n) out[base + 2] = run;           run += v2;
    if (base + 3 < n) out[base + 3] = run;
    if (tid == 255) bsum[blockIdx.x] = s[255];
}

__global__ void scan_fixup(int* __restrict__ off, int* __restrict__ cur, int m,
                           const int* __restrict__ bsumX, int total)
{
    int i = blockIdx.x * blockDim.x + threadIdx.x;
    if (i < m) {
        int v = off[i] + bsumX[i >> 10];
        off[i] = v;
        cur[i] = v;
    }
    if (i == 0) off[m] = total;
}

__global__ void fillM_k(const int* __restrict__ aeiDst, int* cur, int* list)
{
    int i = blockIdx.x * blockDim.x + threadIdx.x;
    if (i < E_AMINO) { int p = atomicAdd(&cur[aeiDst[i]], 1); list[p] = i; }
}

// ------------------------- NNConv -------------------------
__global__ void pack_nn(const float* __restrict__ nw, const float* __restrict__ nb,
                        const float* __restrict__ root, const float* __restrict__ b,
                        float* __restrict__ Wp, float* __restrict__ bp, int d_in)
{
    int idx = blockIdx.x * blockDim.x + threadIdx.x;
    int total = d_in * NCOMB;
    if (idx < total) {
        int i = idx / NCOMB, c = idx % NCOMB;
        float v;
        if (c < 220)      { int d = c / H, o = c % H; v = nw[d * (d_in * H) + i * H + o]; }
        else if (c < 240) { v = nb[i * H + (c - 220)]; }
        else              { v = root[i * H + (c - 240)]; }
        Wp[idx] = v;
    }
    if (idx < NCOMB) bp[idx] = (idx < 240) ? 0.f : b[idx - 240];
}

__global__ void nnconv_edge(const int* __restrict__ ei, const float* __restrict__ ea,
                            float* __restrict__ Cn)
{
    long idx = (long)blockIdx.x * blockDim.x + threadIdx.x;
    if (idx >= (long)E_ATOMS * H) return;
    int e = (int)(idx / H), o = (int)(idx % H);
    int src = ei[e], dst = ei[E_ATOMS + e];
    const float* zrow = Cn + (long)src * NCOMB;
    float m = zrow[220 + o];
    const float* eav = ea + (long)e * D_E;
    #pragma unroll
    for (int d = 0; d < D_E; d++) m = fmaf(eav[d], zrow[d * H + o], m);
    atomicAdd(Cn + (long)dst * NCOMB + 240 + o, m);
}

// ------------------------- amino stage -------------------------
__global__ void aa_init(const float* __restrict__ feat, float* __restrict__ aa)
{
    int idx = blockIdx.x * blockDim.x + threadIdx.x;
    if (idx >= N_AMINO * F_IN) return;
    int n = idx / F_IN, c = idx % F_IN;
    aa[idx] = (c < H) ? 0.f : feat[n * D_AA + (c - H)];
}

__global__ void atom2aa(const float* __restrict__ Cn, const int* __restrict__ lab,
                        float* __restrict__ aa)
{
    long idx = (long)blockIdx.x * blockDim.x + threadIdx.x;
    if (idx >= (long)N_ATOMS * H) return;
    int n = (int)(idx / H), o = (int)(idx % H);
    float v = fmaxf(Cn[(long)n * NCOMB + 240 + o], 0.f);
    atomicAdd(&aa[lab[n] * F_IN + o], v);
}

__global__ void norm_k(const int* __restrict__ aei, const int* __restrict__ off,
                       float* __restrict__ nrm)
{
    int e = blockIdx.x * blockDim.x + threadIdx.x;
    if (e >= E_AMINO) return;
    int src = aei[e], dst = aei[E_AMINO + e];
    float ds = (float)(off[src + 1] - off[src]);
    float dd = (float)(off[dst + 1] - off[dst]);
    float a = (ds > 0.f) ? rsqrtf(ds) : 0.f;
    float c = (dd > 0.f) ? rsqrtf(dd) : 0.f;
    nrm[e] = a * c;
}

// fused: acc[k][n][o] = bias[k][o] + sum_f aa[n][f]*root[k][f][o]
//                      + sum_{e in in(n)} nrm[e]*tmp[k][src(e)][o]
__global__ void arma_fused(const float* __restrict__ aa,
                           const float* __restrict__ root_t,   // [K][F_IN][H_ARMA]
                           const float* __restrict__ bias_t,   // [K][1][H_ARMA]
                           const int* __restrict__ off, const int* __restrict__ list,
                           const int* __restrict__ aeiSrc, const float* __restrict__ nrm,
                           const float* __restrict__ tmp, float* __restrict__ acc)
{
    int idx = blockIdx.x * blockDim.x + threadIdx.x;
    if (idx >= K_ST * N_AMINO * H_ARMA) return;
    int o = idx & (H_ARMA - 1);
    int r = idx >> 7;
    int n = r % N_AMINO;
    int k = r / N_AMINO;

    const float* W  = root_t + (long)k * F_IN * H_ARMA;
    const float* av = aa + n * F_IN;
    float s = bias_t[k * H_ARMA + o];
    #pragma unroll
    for (int f = 0; f < F_IN; f++)
        s = fmaf(av[f], W[f * H_ARMA + o], s);

    long kb = (long)k * N_AMINO;
    int p0 = off[n], p1 = off[n + 1];
    for (int p = p0; p < p1; p++) {
        int e = list[p];
        s = fmaf(nrm[e], tmp[(kb + aeiSrc[e]) * H_ARMA + o], s);
    }
    acc[idx] = s;
}

__global__ void starts_k(const int* __restrict__ ab, int* __restrict__ start)
{
    int n = blockIdx.x * blockDim.x + threadIdx.x;
    if (n >= N_AMINO) return;
    int b = ab[n];
    int prev = (n == 0) ? -1 : ab[n - 1];
    for (int g = prev + 1; g <= b; g++) start[g] = n;
    if (n == N_AMINO - 1)
        for (int g = b + 1; g <= BGRAPH; g++) start[g] = N_AMINO;
}

__global__ void pool_gather(const float* __restrict__ acc, const int* __restrict__ start,
                            float* __restrict__ g)
{
    int idx = blockIdx.x * blockDim.x + threadIdx.x;
    if (idx >= BGRAPH * H_ARMA) return;
    int b = idx >> 7, o = idx & (H_ARMA - 1);
    int n0 = start[b], n1 = start[b + 1];
    float s = 0.f;
    for (int n = n0; n < n1; n++) {
        #pragma unroll
        for (int k = 0; k < K_ST; k++)
            s += fmaxf(acc[((long)k * N_AMINO + n) * H_ARMA + o], 0.f);
    }
    g[idx] = s * (1.f / 3.f);
}

__global__ void final_k(const float* __restrict__ p3, const float* __restrict__ w,
                        const float* __restrict__ b, float* __restrict__ out)
{
    int i = blockIdx.x * blockDim.x + threadIdx.x;
    if (i >= BGRAPH) return;
    float s = b[0];
    #pragma unroll
    for (int f = 0; f < F3; f++) s = fmaf(fmaxf(p3[i * F3 + f], 0.f), w[f], s);
    out[i] = s;
}

// ------------------------- host orchestration -------------------------
static inline int ceil_div(long a, int b) { return (int)((a + b - 1) / b); }

extern "C" void kernel_launch(void* const* d_in, const int* in_sizes, int n_in,
                              void* d_out, int out_size)
{
    const float* x     = (const float*)d_in[0];
    const int*   ei    = (const int*)  d_in[1];
    const float* ea    = (const float*)d_in[2];
    const int*   lab   = (const int*)  d_in[3];
    const float* feat  = (const float*)d_in[4];
    const int*   aei   = (const int*)  d_in[5];
    const int*   ab    = (const int*)  d_in[6];
    const float* nn1_w = (const float*)d_in[7];
    const float* nn1_b = (const float*)d_in[8];
    const float* root1 = (const float*)d_in[9];
    const float* b1    = (const float*)d_in[10];
    const float* nn2_w = (const float*)d_in[11];
    const float* nn2_b = (const float*)d_in[12];
    const float* root2 = (const float*)d_in[13];
    const float* b2    = (const float*)d_in[14];
    const float* nn3_w = (const float*)d_in[15];
    const float* nn3_b = (const float*)d_in[16];
    const float* root3 = (const float*)d_in[17];
    const float* b3    = (const float*)d_in[18];
    const float* arma_init = (const float*)d_in[19];
    const float* arma_w    = (const float*)d_in[20];
    const float* arma_root = (const float*)d_in[21];
    const float* arma_bias = (const float*)d_in[22];
    const float* l1_w = (const float*)d_in[23];
    const float* l1_b = (const float*)d_in[24];
    const float* l2_w = (const float*)d_in[25];
    const float* l2_b = (const float*)d_in[26];
    const float* l3_w = (const float*)d_in[27];
    const float* l3_b = (const float*)d_in[28];
    const float* l4_w = (const float*)d_in[29];
    const float* l4_b = (const float*)d_in[30];

    float *cn1, *cn2, *wp, *bp, *aa, *nrm, *tmp, *accA, *accB, *pool, *p1, *p2, *p3;
    int *offM, *curM, *listM, *bsum, *bsumX, *dummy, *startp;
    cudaGetSymbolAddress((void**)&cn1,  g_cn1);
    cudaGetSymbolAddress((void**)&cn2,  g_cn2);
    cudaGetSymbolAddress((void**)&wp,   g_wpack);
    cudaGetSymbolAddress((void**)&bp,   g_bpack);
    cudaGetSymbolAddress((void**)&aa,   g_aa);
    cudaGetSymbolAddress((void**)&nrm,  g_norm);
    cudaGetSymbolAddress((void**)&tmp,  g_tmp);
    cudaGetSymbolAddress((void**)&accA, g_accA);
    cudaGetSymbolAddress((void**)&accB, g_accB);
    cudaGetSymbolAddress((void**)&pool, g_pool);
    cudaGetSymbolAddress((void**)&p1,   g_p1);
    cudaGetSymbolAddress((void**)&p2,   g_p2);
    cudaGetSymbolAddress((void**)&p3,   g_p3);
    cudaGetSymbolAddress((void**)&offM, g_off_am);
    cudaGetSymbolAddress((void**)&curM, g_cur_am);
    cudaGetSymbolAddress((void**)&listM, g_list_am);
    cudaGetSymbolAddress((void**)&bsum, g_bsum);
    cudaGetSymbolAddress((void**)&bsumX, g_bsumX);
    cudaGetSymbolAddress((void**)&dummy, g_dummy);
    cudaGetSymbolAddress((void**)&startp, g_start);

    const int TB = 256;
    const int* aeiSrc = aei;
    const int* aeiDst = aei + E_AMINO;

    dim3 gN1(ceil_div(N_ATOMS, 128), ceil_div(NCOMB, 64), 1);
    int edgeBlocks = ceil_div((long)E_ATOMS * H, TB);

    // launches 1-3: weight packing
    pack_nn<<<ceil_div(D_IN * NCOMB, TB), TB>>>(nn1_w, nn1_b, root1, b1,
                                                wp, bp, D_IN);
    pack_nn<<<ceil_div(H * NCOMB, TB), TB>>>(nn2_w, nn2_b, root2, b2,
                                             wp + D_IN * NCOMB, bp + NCOMB, H);
    pack_nn<<<ceil_div(H * NCOMB, TB), TB>>>(nn3_w, nn3_b, root3, b3,
                                             wp + 2 * D_IN * NCOMB, bp + 2 * NCOMB, H);
    // launches 4-5: amino CSR count (independent of GEMM)
    zeroM_k<<<ceil_div(N_AMINO, TB), TB>>>(curM);
    countM_k<<<ceil_div(E_AMINO, TB), TB>>>(aeiDst, curM);

    // launch 6: NNConv layer-1 GEMM  (ncu -s 5 -c 1 profiles THIS)
    gemm_tiled<<<gN1, 128>>>(x, D_IN, 0, wp, 0, bp, 0,
                             cn1, NCOMB, 0, N_ATOMS, D_IN, NCOMB, 0);

    // amino CSR finish + norm + starts
    scan_block<<<ceil_div(N_AMINO, 1024), 256>>>(curM, N_AMINO, offM, bsum);
    scan_block<<<1, 256>>>(bsum, ceil_div(N_AMINO, 1024), bsumX, dummy);
    scan_fixup<<<ceil_div(N_AMINO, TB), TB>>>(offM, curM, N_AMINO, bsumX, E_AMINO);
    fillM_k<<<ceil_div(E_AMINO, TB), TB>>>(aeiDst, curM, listM);
    norm_k<<<ceil_div(E_AMINO, TB), TB>>>(aei, offM, nrm);
    starts_k<<<ceil_div(N_AMINO, TB), TB>>>(ab, startp);

    // NNConv edge aggregation (atomics) + layers 2,3
    nnconv_edge<<<edgeBlocks, TB>>>(ei, ea, cn1);
    gemm_tiled<<<gN1, 128>>>(cn1 + 240, NCOMB, 0, wp + D_IN * NCOMB, 0, bp + NCOMB, 0,
                             cn2, NCOMB, 0, N_ATOMS, H, NCOMB, 1);
    nnconv_edge<<<edgeBlocks, TB>>>(ei, ea, cn2);
    gemm_tiled<<<gN1, 128>>>(cn2 + 240, NCOMB, 0, wp + 2 * D_IN * NCOMB, 0, bp + 2 * NCOMB, 0,
                             cn1, NCOMB, 0, N_ATOMS, H, NCOMB, 1);
    nnconv_edge<<<edgeBlocks, TB>>>(ei, ea, cn1);

    // atoms -> amino
    aa_init<<<ceil_div(N_AMINO * F_IN, TB), TB>>>(feat, aa);
    atom2aa<<<ceil_div((long)N_ATOMS * H, TB), TB>>>(cn1, lab, aa);

    // ARMA: K=3 stacks, T=7 layers (2 kernels per layer)
    dim3 gArma(ceil_div(N_AMINO, 128), 2, K_ST);
    int fusedBlocks = ceil_div(K_ST * N_AMINO * H_ARMA, TB);
    float* accP = accA;
    float* accN = accB;
    for (int t = 0; t < T_LAY; t++) {
        if (t == 0) {
            gemm_tiled<<<gArma, 128>>>(
                aa, F_IN, 0,
                arma_init, (long)F_IN * H_ARMA, nullptr, 0,
                tmp, H_ARMA, (long)N_AMINO * H_ARMA,
                N_AMINO, F_IN, H_ARMA, 0);
        } else {
            gemm_tiled<<<gArma, 128>>>(
                accP, H_ARMA, (long)N_AMINO * H_ARMA,
                arma_w + (long)(t - 1) * K_ST * H_ARMA * H_ARMA, (long)H_ARMA * H_ARMA,
                nullptr, 0,
                tmp, H_ARMA, (long)N_AMINO * H_ARMA,
                N_AMINO, H_ARMA, H_ARMA, 1);
        }
        arma_fused<<<fusedBlocks, TB>>>(
            aa,
            arma_root + (long)t * K_ST * F_IN * H_ARMA,
            arma_bias + (long)t * K_ST * H_ARMA,
            offM, listM, aeiSrc, nrm, tmp, accN);
        float* t2 = accP; accP = accN; accN = t2;
    }

    // pooling + head
    pool_gather<<<ceil_div(BGRAPH * H_ARMA, TB), TB>>>(accP, startp, pool);

    dim3 gH1(ceil_div(BGRAPH, 128), ceil_div(F1, 64), 1);
    gemm_tiled<<<gH1, 128>>>(pool, H_ARMA, 0, l1_w, 0, l1_b, 0,
                             p1, F1, 0, BGRAPH, H_ARMA, F1, 0);
    dim3 gH2(ceil_div(BGRAPH, 128), ceil_div(F2, 64), 1);
    gemm_tiled<<<gH2, 128>>>(p1, F1, 0, l2_w, 0, l2_b, 0,
                             p2, F2, 0, BGRAPH, F1, F2, 1);
    dim3 gH3(ceil_div(BGRAPH, 128), ceil_div(F3, 64), 1);
    gemm_tiled<<<gH3, 128>>>(p2, F2, 0, l3_w, 0, l3_b, 0,
                             p3, F3, 0, BGRAPH, F2, F3, 1);
    final_k<<<ceil_div(BGRAPH, TB), TB>>>(p3, l4_w, l4_b, (float*)d_out);
}

// round 5
// speedup vs baseline: 1.2926x; 1.2475x over previous
#include <cuda_runtime.h>
#include <cuda_bf16.h>
#include <cstdint>

#define N_ATOMS 100000
#define E_ATOMS 200000
#define N_AMINO 10240
#define E_AMINO 20480
#define BGRAPH  512
#define D_IN    40
#define D_E     11
#define H       20
#define D_AA    8
#define F_IN    28
#define H_ARMA  128
#define K_ST    3
#define T_LAY   7
#define F1      256
#define F2      128
#define F3      64
#define NCOMB   260     // 220 (z) + 20 (xb) + 20 (root-init)
#define KC      32

// ------------------------- scratch (device globals) -------------------------
__device__ float g_cn1[(long)N_ATOMS * NCOMB];
__device__ float g_cn2[(long)N_ATOMS * NCOMB];
__device__ float g_wpack[3][D_IN * NCOMB];
__device__ float g_bpack[3][NCOMB];
__device__ float g_aa[N_AMINO * F_IN];
__device__ float g_norm[E_AMINO];
__device__ float g_tmp [K_ST * N_AMINO * H_ARMA];
__device__ float g_accA[K_ST * N_AMINO * H_ARMA];
__device__ float g_accB[K_ST * N_AMINO * H_ARMA];
__device__ float g_pool[BGRAPH * H_ARMA];
__device__ float g_p1[BGRAPH * F1];
__device__ float g_p2[BGRAPH * F2];
__device__ float g_p3[BGRAPH * F3];
__device__ int g_off_am[N_AMINO + 1];
__device__ int g_list_am[E_AMINO];
__device__ int g_start[BGRAPH + 1];

// ------------------------- tf32 helpers -------------------------
__device__ __forceinline__ float f2tf32(float x) {
    uint32_t u;
    asm("cvt.rna.tf32.f32 %0, %1;" : "=r"(u) : "f"(x));
    return __uint_as_float(u);
}

__device__ __forceinline__ void mma_tf32(float c[4], const float a[4], const float bb[2]) {
    asm volatile(
        "mma.sync.aligned.m16n8k8.row.col.f32.tf32.tf32.f32 "
        "{%0,%1,%2,%3}, {%4,%5,%6,%7}, {%8,%9}, {%0,%1,%2,%3};\n"
        : "+f"(c[0]), "+f"(c[1]), "+f"(c[2]), "+f"(c[3])
        : "r"(__float_as_uint(a[0])), "r"(__float_as_uint(a[1])),
          "r"(__float_as_uint(a[2])), "r"(__float_as_uint(a[3])),
          "r"(__float_as_uint(bb[0])), "r"(__float_as_uint(bb[1])));
}

// ------------------------- tf32 MMA GEMM -------------------------
// C[bz][m][n] = bias[bz][n] + sum_k relu?(A[bz][m][k]) * W[bz][k][n]
// BM=128, BN=64, BK=16, 256 threads (8 warps, 4x2), warp tile 32x32.
__global__ void __launch_bounds__(256) gemm_mma(
        const float* __restrict__ A, int lda, long strideA,
        const float* __restrict__ W, long strideW,
        const float* __restrict__ Bias, long strideB,
        float* __restrict__ C, int ldc, long strideC,
        int M, int Kd, int N, int reluA)
{
    const int BM = 128, BN = 64, BK = 16;
    __shared__ float sA[BM][20];     // padded: banks conflict-free for frag loads
    __shared__ float sW[BK][72];

    int bz = blockIdx.z;
    const float* Ab = A + (long)bz * strideA;
    const float* Wb = W + (long)bz * strideW;
    float*       Cb = C + (long)bz * strideC;
    int m0 = blockIdx.x * BM;
    int n0 = blockIdx.y * BN;
    int tid = threadIdx.x;
    int warp = tid >> 5, lane = tid & 31;
    int wm = warp >> 1, wn = warp & 1;
    int gid = lane >> 2, tig = lane & 3;

    float c[2][4][4];
    #pragma unroll
    for (int mt = 0; mt < 2; mt++)
        #pragma unroll
        for (int nt = 0; nt < 4; nt++)
            #pragma unroll
            for (int q = 0; q < 4; q++) c[mt][nt][q] = 0.f;

    for (int k0 = 0; k0 < Kd; k0 += BK) {
        // stage A [128][16]
        #pragma unroll
        for (int i = 0; i < 2; i++) {
            int idx = tid + i * 256;       // 0..511 float4 slots
            int m  = idx >> 2;
            int kk = (idx & 3) << 2;
            int row = m0 + m, kg = k0 + kk;
            float4 a = make_float4(0.f, 0.f, 0.f, 0.f);
            if (row < M) {
                if (kg + 3 < Kd) a = *(const float4*)(Ab + (long)row * lda + kg);
                else {
                    if (kg     < Kd) a.x = Ab[(long)row * lda + kg];
                    if (kg + 1 < Kd) a.y = Ab[(long)row * lda + kg + 1];
                    if (kg + 2 < Kd) a.z = Ab[(long)row * lda + kg + 2];
                    if (kg + 3 < Kd) a.w = Ab[(long)row * lda + kg + 3];
                }
            }
            if (reluA) {
                a.x = fmaxf(a.x, 0.f); a.y = fmaxf(a.y, 0.f);
                a.z = fmaxf(a.z, 0.f); a.w = fmaxf(a.w, 0.f);
            }
            a.x = f2tf32(a.x); a.y = f2tf32(a.y);
            a.z = f2tf32(a.z); a.w = f2tf32(a.w);
            *(float4*)(&sA[m][kk]) = a;
        }
        // stage W [16][64]
        {
            int kk = tid >> 4;
            int nn = (tid & 15) << 2;
            int kg = k0 + kk, n = n0 + nn;
            float4 w = make_float4(0.f, 0.f, 0.f, 0.f);
            if (kg < Kd) {
                const float* wr = Wb + (long)kg * N;
                if (n + 3 < N) w = *(const float4*)(wr + n);
                else {
                    if (n     < N) w.x = wr[n];
                    if (n + 1 < N) w.y = wr[n + 1];
                    if (n + 2 < N) w.z = wr[n + 2];
                    if (n + 3 < N) w.w = wr[n + 3];
                }
            }
            w.x = f2tf32(w.x); w.y = f2tf32(w.y);
            w.z = f2tf32(w.z); w.w = f2tf32(w.w);
            *(float4*)(&sW[kk][nn]) = w;
        }
        __syncthreads();

        #pragma unroll
        for (int ks = 0; ks < 2; ks++) {
            int kb = ks * 8;
            float afr[2][4], bfr[4][2];
            #pragma unroll
            for (int mt = 0; mt < 2; mt++) {
                int r = wm * 32 + mt * 16;
                afr[mt][0] = sA[r + gid    ][kb + tig];
                afr[mt][1] = sA[r + gid + 8][kb + tig];
                afr[mt][2] = sA[r + gid    ][kb + tig + 4];
                afr[mt][3] = sA[r + gid + 8][kb + tig + 4];
            }
            #pragma unroll
            for (int nt = 0; nt < 4; nt++) {
                int cc = wn * 32 + nt * 8 + gid;
                bfr[nt][0] = sW[kb + tig    ][cc];
                bfr[nt][1] = sW[kb + tig + 4][cc];
            }
            #pragma unroll
            for (int mt = 0; mt < 2; mt++)
                #pragma unroll
                for (int nt = 0; nt < 4; nt++)
                    mma_tf32(c[mt][nt], afr[mt], bfr[nt]);
        }
        __syncthreads();
    }

    // epilogue
    #pragma unroll
    for (int mt = 0; mt < 2; mt++) {
        #pragma unroll
        for (int nt = 0; nt < 4; nt++) {
            int row = m0 + wm * 32 + mt * 16 + gid;
            int col = n0 + wn * 32 + nt * 8 + 2 * tig;
            float bv0 = 0.f, bv1 = 0.f;
            if (Bias) {
                if (col     < N) bv0 = Bias[(long)bz * strideB + col];
                if (col + 1 < N) bv1 = Bias[(long)bz * strideB + col + 1];
            }
            if (row < M) {
                if (col + 1 < N) {
                    float2 o = make_float2(c[mt][nt][0] + bv0, c[mt][nt][1] + bv1);
                    *(float2*)(Cb + (long)row * ldc + col) = o;
                } else if (col < N) {
                    Cb[(long)row * ldc + col] = c[mt][nt][0] + bv0;
                }
            }
            int row2 = row + 8;
            if (row2 < M) {
                if (col + 1 < N) {
                    float2 o = make_float2(c[mt][nt][2] + bv0, c[mt][nt][3] + bv1);
                    *(float2*)(Cb + (long)row2 * ldc + col) = o;
                } else if (col < N) {
                    Cb[(long)row2 * ldc + col] = c[mt][nt][2] + bv0;
                }
            }
        }
    }
}

// ------------------------- FFMA GEMM (small head layers) -------------------------
__global__ void __launch_bounds__(128) gemm_tiled(
        const float* __restrict__ A, int lda, long strideA,
        const float* __restrict__ W, long strideW,
        const float* __restrict__ Bias, long strideB,
        float* __restrict__ C, int ldc, long strideC,
        int M, int Kd, int N, int reluA)
{
    const int BM = 128, BN = 64;
    __shared__ float sA[BM][KC + 1];
    __shared__ float sW[KC][BN];

    int b = blockIdx.z;
    const float* Ab = A + (long)b * strideA;
    const float* Wb = W + (long)b * strideW;
    float*       Cb = C + (long)b * strideC;
    int m0 = blockIdx.x * BM;
    int n0 = blockIdx.y * BN;
    int tid = threadIdx.x;

    int ct = tid & 7, rt = tid >> 3;
    int mbase = rt * 8, nb = ct * 8;

    float acc[8][8];
    #pragma unroll
    for (int i = 0; i < 8; i++)
        #pragma unroll
        for (int j = 0; j < 8; j++) acc[i][j] = 0.f;

    for (int kc0 = 0; kc0 < Kd; kc0 += KC) {
        int kc = min(KC, Kd - kc0);
        int wtot = kc * (BN / 4);
        for (int idx = tid; idx < wtot; idx += 128) {
            int k = idx >> 4, n4 = (idx & 15) << 2, n = n0 + n4;
            const float* wr = Wb + (long)(kc0 + k) * N;
            float4 w;
            if (n + 3 < N) w = *(const float4*)(wr + n);
            else {
                w.x = (n < N) ? wr[n] : 0.f;
                w.y = (n + 1 < N) ? wr[n + 1] : 0.f;
                w.z = (n + 2 < N) ? wr[n + 2] : 0.f;
                w.w = (n + 3 < N) ? wr[n + 3] : 0.f;
            }
            *(float4*)(&sW[k][n4]) = w;
        }
        int kq = kc >> 2, atot = BM * kq;
        for (int idx = tid; idx < atot; idx += 128) {
            int m = idx / kq, k4 = (idx - m * kq) << 2, row = m0 + m;
            float4 a = make_float4(0.f, 0.f, 0.f, 0.f);
            if (row < M) a = *(const float4*)(Ab + (long)row * lda + kc0 + k4);
            if (reluA) {
                a.x = fmaxf(a.x, 0.f); a.y = fmaxf(a.y, 0.f);
                a.z = fmaxf(a.z, 0.f); a.w = fmaxf(a.w, 0.f);
            }
            sA[m][k4] = a.x; sA[m][k4+1] = a.y; sA[m][k4+2] = a.z; sA[m][k4+3] = a.w;
        }
        __syncthreads();
        for (int k = 0; k < kc; k++) {
            float4 w0 = *(const float4*)(&sW[k][nb]);
            float4 w1 = *(const float4*)(&sW[k][nb + 4]);
            #pragma unroll
            for (int i = 0; i < 8; i++) {
                float a = sA[mbase + i][k];
                acc[i][0] = fmaf(a, w0.x, acc[i][0]);
                acc[i][1] = fmaf(a, w0.y, acc[i][1]);
                acc[i][2] = fmaf(a, w0.z, acc[i][2]);
                acc[i][3] = fmaf(a, w0.w, acc[i][3]);
                acc[i][4] = fmaf(a, w1.x, acc[i][4]);
                acc[i][5] = fmaf(a, w1.y, acc[i][5]);
                acc[i][6] = fmaf(a, w1.z, acc[i][6]);
                acc[i][7] = fmaf(a, w1.w, acc[i][7]);
            }
        }
        __syncthreads();
    }

    float bv[8];
    #pragma unroll
    for (int j = 0; j < 8; j++) {
        int n = n0 + nb + j;
        bv[j] = (Bias && n < N) ? Bias[(long)b * strideB + n] : 0.f;
    }
    bool fullN = (n0 + nb + 7) < N;
    #pragma unroll
    for (int i = 0; i < 8; i++) {
        int row = m0 + mbase + i;
        if (row >= M) break;
        float* cr = Cb + (long)row * ldc + n0 + nb;
        if (fullN) {
            float4 o0 = make_float4(acc[i][0]+bv[0], acc[i][1]+bv[1], acc[i][2]+bv[2], acc[i][3]+bv[3]);
            float4 o1 = make_float4(acc[i][4]+bv[4], acc[i][5]+bv[5], acc[i][6]+bv[6], acc[i][7]+bv[7]);
            *(float4*)(cr) = o0;
            *(float4*)(cr + 4) = o1;
        } else {
            #pragma unroll
            for (int j = 0; j < 8; j++) {
                int n = n0 + nb + j;
                if (n < N) cr[j] = acc[i][j] + bv[j];
            }
        }
    }
}

// ------------------------- single-block prep: amino CSR + norm + starts -------------------------
__global__ void prep_k(const int* __restrict__ aeiSrc, const int* __restrict__ aeiDst,
                       const int* __restrict__ ab,
                       int* __restrict__ offM, int* __restrict__ listM,
                       float* __restrict__ nrm, int* __restrict__ startp)
{
    extern __shared__ int sh[];
    int* cnt  = sh;                    // N_AMINO
    int* cur  = sh + N_AMINO;          // N_AMINO
    int* part = sh + 2 * N_AMINO;      // 1024
    int tid = threadIdx.x;

    for (int i = tid; i < N_AMINO; i += 1024) cnt[i] = 0;
    __syncthreads();
    for (int e = tid; e < E_AMINO; e += 1024) atomicAdd(&cnt[aeiDst[e]], 1);
    __syncthreads();
    for (int e = tid; e < E_AMINO; e += 1024) {
        int s = aeiSrc[e], d = aeiDst[e];
        int cs = cnt[s], cd = cnt[d];
        float a = cs > 0 ? rsqrtf((float)cs) : 0.f;
        float c = cd > 0 ? rsqrtf((float)cd) : 0.f;
        nrm[e] = a * c;
    }
    __syncthreads();
    // exclusive scan of cnt (10 elems per thread + block scan)
    int base = tid * 10;
    int loc[10];
    int s = 0;
    #pragma unroll
    for (int j = 0; j < 10; j++) { loc[j] = cnt[base + j]; s += loc[j]; }
    part[tid] = s;
    __syncthreads();
    for (int off = 1; off < 1024; off <<= 1) {
        int v = part[tid];
        int o = (tid >= off) ? part[tid - off] : 0;
        __syncthreads();
        part[tid] = v + o;
        __syncthreads();
    }
    int run = part[tid] - s;
    #pragma unroll
    for (int j = 0; j < 10; j++) {
        int cc = loc[j];
        cnt[base + j] = run;
        cur[base + j] = run;
        run += cc;
    }
    __syncthreads();
    for (int i = tid; i < N_AMINO; i += 1024) offM[i] = cnt[i];
    if (tid == 0) offM[N_AMINO] = E_AMINO;
    for (int e = tid; e < E_AMINO; e += 1024) {
        int p = atomicAdd(&cur[aeiDst[e]], 1);
        listM[p] = e;
    }
    for (int n = tid; n < N_AMINO; n += 1024) {
        int bv = ab[n];
        int prev = (n == 0) ? -1 : ab[n - 1];
        for (int g = prev + 1; g <= bv; g++) startp[g] = n;
        if (n == N_AMINO - 1)
            for (int g = bv + 1; g <= BGRAPH; g++) startp[g] = N_AMINO;
    }
}

// ------------------------- weight packing (all 3 layers) -------------------------
__global__ void pack3_k(const float* __restrict__ nw1, const float* __restrict__ nb1,
                        const float* __restrict__ r1,  const float* __restrict__ bb1,
                        const float* __restrict__ nw2, const float* __restrict__ nb2,
                        const float* __restrict__ r2,  const float* __restrict__ bb2,
                        const float* __restrict__ nw3, const float* __restrict__ nb3,
                        const float* __restrict__ r3,  const float* __restrict__ bb3,
                        float* __restrict__ Wp, float* __restrict__ bp)
{
    int layer = blockIdx.y;
    const float *nw, *nb, *root, *b;
    int d_in;
    if (layer == 0)      { nw = nw1; nb = nb1; root = r1; b = bb1; d_in = D_IN; }
    else if (layer == 1) { nw = nw2; nb = nb2; root = r2; b = bb2; d_in = H; }
    else                 { nw = nw3; nb = nb3; root = r3; b = bb3; d_in = H; }
    float* W   = Wp + layer * D_IN * NCOMB;
    float* bpp = bp + layer * NCOMB;

    int idx = blockIdx.x * blockDim.x + threadIdx.x;
    int total = d_in * NCOMB;
    if (idx < total) {
        int i = idx / NCOMB, c = idx % NCOMB;
        float v;
        if (c < 220)      { int d = c / H, o = c % H; v = nw[d * (d_in * H) + i * H + o]; }
        else if (c < 240) { v = nb[i * H + (c - 220)]; }
        else              { v = root[i * H + (c - 240)]; }
        W[idx] = v;
    }
    if (idx < NCOMB) bpp[idx] = (idx < 240) ? 0.f : b[idx - 240];
}

// ------------------------- NNConv edge aggregation -------------------------
__global__ void nnconv_edge(const int* __restrict__ ei, const float* __restrict__ ea,
                            float* __restrict__ Cn)
{
    long idx = (long)blockIdx.x * blockDim.x + threadIdx.x;
    if (idx >= (long)E_ATOMS * H) return;
    int e = (int)(idx / H), o = (int)(idx % H);
    int src = ei[e], dst = ei[E_ATOMS + e];
    const float* zrow = Cn + (long)src * NCOMB;
    float m = zrow[220 + o];
    const float* eav = ea + (long)e * D_E;
    #pragma unroll
    for (int d = 0; d < D_E; d++) m = fmaf(eav[d], zrow[d * H + o], m);
    atomicAdd(Cn + (long)dst * NCOMB + 240 + o, m);
}

// ------------------------- amino stage -------------------------
__global__ void aa_init(const float* __restrict__ feat, float* __restrict__ aa)
{
    int idx = blockIdx.x * blockDim.x + threadIdx.x;
    if (idx >= N_AMINO * F_IN) return;
    int n = idx / F_IN, c = idx % F_IN;
    aa[idx] = (c < H) ? 0.f : feat[n * D_AA + (c - H)];
}

__global__ void atom2aa(const float* __restrict__ Cn, const int* __restrict__ lab,
                        float* __restrict__ aa)
{
    long idx = (long)blockIdx.x * blockDim.x + threadIdx.x;
    if (idx >= (long)N_ATOMS * H) return;
    int n = (int)(idx / H), o = (int)(idx % H);
    float v = fmaxf(Cn[(long)n * NCOMB + 240 + o], 0.f);
    atomicAdd(&aa[lab[n] * F_IN + o], v);
}

// fused: acc[k][n][o] = bias[k][o] + sum_f aa[n][f]*root[k][f][o]
//                      + sum_{e in in(n)} nrm[e]*tmp[k][src(e)][o]
__global__ void arma_fused(const float* __restrict__ aa,
                           const float* __restrict__ root_t,
                           const float* __restrict__ bias_t,
                           const int* __restrict__ off, const int* __restrict__ list,
                           const int* __restrict__ aeiSrc, const float* __restrict__ nrm,
                           const float* __restrict__ tmp, float* __restrict__ acc)
{
    int idx = blockIdx.x * blockDim.x + threadIdx.x;
    if (idx >= K_ST * N_AMINO * H_ARMA) return;
    int o = idx & (H_ARMA - 1);
    int r = idx >> 7;
    int n = r % N_AMINO;
    int k = r / N_AMINO;

    const float* W  = root_t + (long)k * F_IN * H_ARMA;
    const float* av = aa + n * F_IN;
    float s = bias_t[k * H_ARMA + o];
    #pragma unroll
    for (int f = 0; f < F_IN; f++)
        s = fmaf(av[f], W[f * H_ARMA + o], s);

    long kb = (long)k * N_AMINO;
    int p0 = off[n], p1 = off[n + 1];
    for (int p = p0; p < p1; p++) {
        int e = list[p];
        s = fmaf(nrm[e], tmp[(kb + aeiSrc[e]) * H_ARMA + o], s);
    }
    acc[idx] = s;
}

__global__ void pool_gather(const float* __restrict__ acc, const int* __restrict__ start,
                            float* __restrict__ g)
{
    int idx = blockIdx.x * blockDim.x + threadIdx.x;
    if (idx >= BGRAPH * H_ARMA) return;
    int b = idx >> 7, o = idx & (H_ARMA - 1);
    int n0 = start[b], n1 = start[b + 1];
    float s = 0.f;
    for (int n = n0; n < n1; n++) {
        #pragma unroll
        for (int k = 0; k < K_ST; k++)
            s += fmaxf(acc[((long)k * N_AMINO + n) * H_ARMA + o], 0.f);
    }
    g[idx] = s * (1.f / 3.f);
}

__global__ void final_k(const float* __restrict__ p3, const float* __restrict__ w,
                        const float* __restrict__ b, float* __restrict__ out)
{
    int i = blockIdx.x * blockDim.x + threadIdx.x;
    if (i >= BGRAPH) return;
    float s = b[0];
    #pragma unroll
    for (int f = 0; f < F3; f++) s = fmaf(fmaxf(p3[i * F3 + f], 0.f), w[f], s);
    out[i] = s;
}

// ------------------------- host orchestration -------------------------
static inline int ceil_div(long a, int b) { return (int)((a + b - 1) / b); }

extern "C" void kernel_launch(void* const* d_in, const int* in_sizes, int n_in,
                              void* d_out, int out_size)
{
    const float* x     = (const float*)d_in[0];
    const int*   ei    = (const int*)  d_in[1];
    const float* ea    = (const float*)d_in[2];
    const int*   lab   = (const int*)  d_in[3];
    const float* feat  = (const float*)d_in[4];
    const int*   aei   = (const int*)  d_in[5];
    const int*   ab    = (const int*)  d_in[6];
    const float* nn1_w = (const float*)d_in[7];
    const float* nn1_b = (const float*)d_in[8];
    const float* root1 = (const float*)d_in[9];
    const float* b1    = (const float*)d_in[10];
    const float* nn2_w = (const float*)d_in[11];
    const float* nn2_b = (const float*)d_in[12];
    const float* root2 = (const float*)d_in[13];
    const float* b2    = (const float*)d_in[14];
    const float* nn3_w = (const float*)d_in[15];
    const float* nn3_b = (const float*)d_in[16];
    const float* root3 = (const float*)d_in[17];
    const float* b3    = (const float*)d_in[18];
    const float* arma_init = (const float*)d_in[19];
    const float* arma_w    = (const float*)d_in[20];
    const float* arma_root = (const float*)d_in[21];
    const float* arma_bias = (const float*)d_in[22];
    const float* l1_w = (const float*)d_in[23];
    const float* l1_b = (const float*)d_in[24];
    const float* l2_w = (const float*)d_in[25];
    const float* l2_b = (const float*)d_in[26];
    const float* l3_w = (const float*)d_in[27];
    const float* l3_b = (const float*)d_in[28];
    const float* l4_w = (const float*)d_in[29];
    const float* l4_b = (const float*)d_in[30];

    float *cn1, *cn2, *wp, *bp, *aa, *nrm, *tmp, *accA, *accB, *pool, *p1, *p2, *p3;
    int *offM, *listM, *startp;
    cudaGetSymbolAddress((void**)&cn1,  g_cn1);
    cudaGetSymbolAddress((void**)&cn2,  g_cn2);
    cudaGetSymbolAddress((void**)&wp,   g_wpack);
    cudaGetSymbolAddress((void**)&bp,   g_bpack);
    cudaGetSymbolAddress((void**)&aa,   g_aa);
    cudaGetSymbolAddress((void**)&nrm,  g_norm);
    cudaGetSymbolAddress((void**)&tmp,  g_tmp);
    cudaGetSymbolAddress((void**)&accA, g_accA);
    cudaGetSymbolAddress((void**)&accB, g_accB);
    cudaGetSymbolAddress((void**)&pool, g_pool);
    cudaGetSymbolAddress((void**)&p1,   g_p1);
    cudaGetSymbolAddress((void**)&p2,   g_p2);
    cudaGetSymbolAddress((void**)&p3,   g_p3);
    cudaGetSymbolAddress((void**)&offM, g_off_am);
    cudaGetSymbolAddress((void**)&listM, g_list_am);
    cudaGetSymbolAddress((void**)&startp, g_start);

    static bool attr_set = false;
    if (!attr_set) {
        cudaFuncSetAttribute(prep_k, cudaFuncAttributeMaxDynamicSharedMemorySize,
                             (2 * N_AMINO + 1024) * sizeof(int));
        attr_set = true;
    }

    const int TB = 256;
    const int* aeiSrc = aei;
    const int* aeiDst = aei + E_AMINO;

    dim3 gN1(ceil_div(N_ATOMS, 128), ceil_div(NCOMB, 64), 1);  // (782, 5)
    int edgeBlocks = ceil_div((long)E_ATOMS * H, TB);

    // prep (1 launch) + packing (1 launch)
    prep_k<<<1, 1024, (2 * N_AMINO + 1024) * sizeof(int)>>>(
        aeiSrc, aeiDst, ab, offM, listM, nrm, startp);
    dim3 gPack(ceil_div(D_IN * NCOMB, TB), 3);
    pack3_k<<<gPack, TB>>>(nn1_w, nn1_b, root1, b1,
                           nn2_w, nn2_b, root2, b2,
                           nn3_w, nn3_b, root3, b3, wp, bp);

    // NNConv layers (tf32 MMA GEMM + atomic edge aggregation)
    gemm_mma<<<gN1, 256>>>(x, D_IN, 0, wp, 0, bp, 0,
                           cn1, NCOMB, 0, N_ATOMS, D_IN, NCOMB, 0);
    nnconv_edge<<<edgeBlocks, TB>>>(ei, ea, cn1);
    gemm_mma<<<gN1, 256>>>(cn1 + 240, NCOMB, 0, wp + D_IN * NCOMB, 0, bp + NCOMB, 0,
                           cn2, NCOMB, 0, N_ATOMS, H, NCOMB, 1);
    nnconv_edge<<<edgeBlocks, TB>>>(ei, ea, cn2);
    gemm_mma<<<gN1, 256>>>(cn2 + 240, NCOMB, 0, wp + 2 * D_IN * NCOMB, 0, bp + 2 * NCOMB, 0,
                           cn1, NCOMB, 0, N_ATOMS, H, NCOMB, 1);
    nnconv_edge<<<edgeBlocks, TB>>>(ei, ea, cn1);

    // atoms -> amino
    aa_init<<<ceil_div(N_AMINO * F_IN, TB), TB>>>(feat, aa);
    atom2aa<<<ceil_div((long)N_ATOMS * H, TB), TB>>>(cn1, lab, aa);

    // ARMA: K=3 stacks, T=7 layers (gemm_mma + arma_fused per layer)
    dim3 gArma(ceil_div(N_AMINO, 128), 2, K_ST);   // (80, 2, 3)
    int fusedBlocks = ceil_div(K_ST * N_AMINO * H_ARMA, TB);
    float* accP = accA;
    float* accN = accB;
    for (int t = 0; t < T_LAY; t++) {
        if (t == 0) {
            gemm_mma<<<gArma, 256>>>(
                aa, F_IN, 0,
                arma_init, (long)F_IN * H_ARMA, nullptr, 0,
                tmp, H_ARMA, (long)N_AMINO * H_ARMA,
                N_AMINO, F_IN, H_ARMA, 0);
        } else {
            gemm_mma<<<gArma, 256>>>(
                accP, H_ARMA, (long)N_AMINO * H_ARMA,
                arma_w + (long)(t - 1) * K_ST * H_ARMA * H_ARMA, (long)H_ARMA * H_ARMA,
                nullptr, 0,
                tmp, H_ARMA, (long)N_AMINO * H_ARMA,
                N_AMINO, H_ARMA, H_ARMA, 1);
        }
        arma_fused<<<fusedBlocks, TB>>>(
            aa,
            arma_root + (long)t * K_ST * F_IN * H_ARMA,
            arma_bias + (long)t * K_ST * H_ARMA,
            offM, listM, aeiSrc, nrm, tmp, accN);
        float* t2 = accP; accP = accN; accN = t2;
    }

    // pooling + head
    pool_gather<<<ceil_div(BGRAPH * H_ARMA, TB), TB>>>(accP, startp, pool);

    dim3 gH1(ceil_div(BGRAPH, 128), ceil_div(F1, 64), 1);
    gemm_tiled<<<gH1, 128>>>(pool, H_ARMA, 0, l1_w, 0, l1_b, 0,
                             p1, F1, 0, BGRAPH, H_ARMA, F1, 0);
    dim3 gH2(ceil_div(BGRAPH, 128), ceil_div(F2, 64), 1);
    gemm_tiled<<<gH2, 128>>>(p1, F1, 0, l2_w, 0, l2_b, 0,
                             p2, F2, 0, BGRAPH, F1, F2, 1);
    dim3 gH3(ceil_div(BGRAPH, 128), ceil_div(F3, 64), 1);
    gemm_tiled<<<gH3, 128>>>(p2, F2, 0, l3_w, 0, l3_b, 0,
                             p3, F3, 0, BGRAPH, F2, F3, 1);
    final_k<<<ceil_div(BGRAPH, TB), TB>>>(p3, l4_w, l4_b, (float*)d_out);
}